// round 14
// baseline (speedup 1.0000x reference)
#include <cuda_runtime.h>
#include <cuda_bf16.h>
#include <math.h>

#define BB 2
#define SS 2048
#define DD 1024
#define HH 16
#define DHD 64
#define NROWS (BB*SS)        // 4096
#define NBH (BB*HH)          // 32
#define ATTN_SCALE 0.125f
#define CSHIFT 8.0f          // constant softmax shift (shift-invariant)

// ---------------------------------------------------------------------------
// Device-global scratch: bf16 hi/lo planes.
// ---------------------------------------------------------------------------
__device__ __nv_bfloat16 g_Xh[3][NROWS*DD];   // split query/key/value
__device__ __nv_bfloat16 g_Xl[3][NROWS*DD];
__device__ __nv_bfloat16 g_Wh[4][DD*DD];      // split Wq/Wk/Wv/Wo
__device__ __nv_bfloat16 g_Wl[4][DD*DD];
__device__ __nv_bfloat16 g_Qh[NBH*SS*DHD];    // [B,H,S,dh] planes
__device__ __nv_bfloat16 g_Ql[NBH*SS*DHD];
__device__ __nv_bfloat16 g_Kh[NBH*SS*DHD];
__device__ __nv_bfloat16 g_Kl[NBH*SS*DHD];
__device__ __nv_bfloat16 g_Vh[NBH*SS*DHD];
__device__ __nv_bfloat16 g_Vl[NBH*SS*DHD];
__device__ __nv_bfloat16 g_Oh[NROWS*DD];      // concat-heads planes
__device__ __nv_bfloat16 g_Ol[NROWS*DD];

// ===========================================================================
// helpers
// ===========================================================================
__device__ __forceinline__ unsigned s2u(const void* p) {
    unsigned a;
    asm("{ .reg .u64 t; cvta.to.shared.u64 t, %1; cvt.u32.u64 %0, t; }"
        : "=r"(a) : "l"(p));
    return a;
}
__device__ __forceinline__ void mma16816(float* c, const unsigned* a, const unsigned* b) {
    asm volatile(
        "mma.sync.aligned.m16n8k16.row.col.f32.bf16.bf16.f32 "
        "{%0,%1,%2,%3}, {%4,%5,%6,%7}, {%8,%9}, {%0,%1,%2,%3};"
        : "+f"(c[0]), "+f"(c[1]), "+f"(c[2]), "+f"(c[3])
        : "r"(a[0]), "r"(a[1]), "r"(a[2]), "r"(a[3]), "r"(b[0]), "r"(b[1]));
}
__device__ __forceinline__ void ldm_x4(unsigned* r, unsigned addr) {
    asm volatile("ldmatrix.sync.aligned.m8n8.x4.shared.b16 {%0,%1,%2,%3}, [%4];"
        : "=r"(r[0]), "=r"(r[1]), "=r"(r[2]), "=r"(r[3]) : "r"(addr));
}
__device__ __forceinline__ void ldm_x4_t(unsigned* r, unsigned addr) {
    asm volatile("ldmatrix.sync.aligned.m8n8.x4.trans.shared.b16 {%0,%1,%2,%3}, [%4];"
        : "=r"(r[0]), "=r"(r[1]), "=r"(r[2]), "=r"(r[3]) : "r"(addr));
}
// Truncation split of a pair of fp32 into packed bf16 hi/lo planes.
// hi = top 16 bits (1 PRMT for the pair); lo = x - hi (exact), packed cvt.
__device__ __forceinline__ void split_pair(float a, float b,
                                           unsigned& hi2, unsigned& lo2) {
    unsigned ua = __float_as_uint(a), ub = __float_as_uint(b);
    asm("prmt.b32 %0, %1, %2, 0x7632;" : "=r"(hi2) : "r"(ua), "r"(ub));
    float ha = __uint_as_float(ua & 0xFFFF0000u);
    float hb = __uint_as_float(ub & 0xFFFF0000u);
    float la = a - ha, lb = b - hb;
    asm("cvt.rn.bf16x2.f32 %0, %1, %2;" : "=r"(lo2) : "f"(lb), "f"(la));
}
__device__ __forceinline__ void cpa16(unsigned dst, const void* src) {
    asm volatile("cp.async.cg.shared.global [%0], [%1], 16;" :: "r"(dst), "l"(src));
}
#define CP_COMMIT() asm volatile("cp.async.commit_group;" ::: "memory")
#define CP_WAIT0()  asm volatile("cp.async.wait_group 0;" ::: "memory")
#define CP_WAIT1()  asm volatile("cp.async.wait_group 1;" ::: "memory")

// ---------------------------------------------------------------------------
// Prep: split inputs (q/k/v) and weights into bf16 hi/lo planes once.
// ---------------------------------------------------------------------------
__global__ __launch_bounds__(256) void prep_split(
    const float* __restrict__ q, const float* __restrict__ k,
    const float* __restrict__ v,
    const float* __restrict__ w0, const float* __restrict__ w1,
    const float* __restrict__ w2, const float* __restrict__ w3)
{
    const int z = blockIdx.y;
    const float* src;
    __nv_bfloat16 *dh, *dl;
    int n4;
    if (z < 3) {
        src = (z == 0) ? q : (z == 1) ? k : v;
        dh = g_Xh[z]; dl = g_Xl[z]; n4 = NROWS*DD/4;
    } else {
        int w = z - 3;
        src = (w == 0) ? w0 : (w == 1) ? w1 : (w == 2) ? w2 : w3;
        dh = g_Wh[w]; dl = g_Wl[w]; n4 = DD*DD/4;
    }
    for (int i = blockIdx.x * 256 + threadIdx.x; i < n4; i += gridDim.x * 256) {
        float4 x = ((const float4*)src)[i];
        unsigned h01, l01, h23, l23;
        split_pair(x.x, x.y, h01, l01);
        split_pair(x.z, x.w, h23, l23);
        ((uint2*)dh)[i] = make_uint2(h01, h23);
        ((uint2*)dl)[i] = make_uint2(l01, l23);
    }
}

// ---------------------------------------------------------------------------
// Projection GEMM (HMMA, bf16 planes, cp.async double-buffered).
// Sequential launches keep the ~41 MB working set L2-resident.
// mode 0/1/2 -> Q/K/V planes; 3 -> fp32 out.
// ---------------------------------------------------------------------------
#define PROWB 80
#define PPLANE 10240
#define PSTAGE (4*PPLANE)
#define PROJ_SMEM (2*PSTAGE)               // 81920

__global__ __launch_bounds__(256) void proj_gemm_bf(
    const float* __restrict__ bias, float* __restrict__ out_ext, int mode)
{
    extern __shared__ char smem[];
    const unsigned sb = s2u(smem);
    const int tid = threadIdx.x, wid = tid >> 5, lane = tid & 31;
    const int wm = wid >> 1, wn = wid & 1;
    const int rowBase = blockIdx.y * 128;
    const int colBase = blockIdx.x * 128;

    const __nv_bfloat16* Xh = (mode == 3) ? g_Oh : g_Xh[mode];
    const __nv_bfloat16* Xl = (mode == 3) ? g_Ol : g_Xl[mode];
    const __nv_bfloat16* Wh = g_Wh[mode];
    const __nv_bfloat16* Wl = g_Wl[mode];

    float acc[2][8][4];
#pragma unroll
    for (int i = 0; i < 2; i++)
#pragma unroll
        for (int j = 0; j < 8; j++)
#pragma unroll
            for (int v = 0; v < 4; v++) acc[i][j][v] = 0.f;

    auto ISSUE = [&](int c) {
        const int k0 = c * 32;
        const unsigned st = sb + (unsigned)(c & 1) * PSTAGE;
        for (int i = tid; i < 2048; i += 256) {
            int pl = i >> 9, r = (i >> 2) & 127, sg = i & 3;
            const __nv_bfloat16* srcp;
            if (pl == 0)      srcp = Xh + (size_t)(rowBase + r) * DD + k0 + sg*8;
            else if (pl == 1) srcp = Xl + (size_t)(rowBase + r) * DD + k0 + sg*8;
            else if (pl == 2) srcp = Wh + (size_t)(colBase + r) * DD + k0 + sg*8;
            else              srcp = Wl + (size_t)(colBase + r) * DD + k0 + sg*8;
            cpa16(st + (unsigned)pl * PPLANE + (unsigned)r * PROWB + sg*16, srcp);
        }
    };

    ISSUE(0); CP_COMMIT();

    const int a_row = wm*32 + (lane & 15);
    const int a_c8  = (lane >> 4) << 3;
    const int b_row = wn*64 + (((lane >> 4) & 1) << 3) + (lane & 7);
    const int b_c8  = ((lane >> 3) & 1) << 3;

    for (int c = 0; c < 32; c++) {
        if (c < 31) { ISSUE(c + 1); CP_COMMIT(); CP_WAIT1(); }
        else        { CP_WAIT0(); }
        __syncthreads();

        const unsigned sA  = sb + (unsigned)(c & 1) * PSTAGE;
        const unsigned sAl = sA + PPLANE;
        const unsigned sBh = sA + 2*PPLANE;
        const unsigned sBl = sA + 3*PPLANE;

#pragma unroll
        for (int ks = 0; ks < 2; ks++) {
            unsigned ahi[8], alo[8];
#pragma unroll
            for (int t = 0; t < 2; t++) {
                unsigned ar = (unsigned)(a_row + t*16) * PROWB
                            + (unsigned)(ks*16 + a_c8) * 2;
                ldm_x4(ahi + t*4, sA  + ar);
                ldm_x4(alo + t*4, sAl + ar);
            }
#pragma unroll
            for (int jp = 0; jp < 4; jp++) {
                unsigned br = (unsigned)(b_row + jp*16) * PROWB
                            + (unsigned)(ks*16 + b_c8) * 2;
                unsigned bhi[4], blo[4];
                ldm_x4(bhi, sBh + br);
                ldm_x4(blo, sBl + br);
#pragma unroll
                for (int tn = 0; tn < 2; tn++) {
#pragma unroll
                    for (int mi = 0; mi < 2; mi++) {
                        float* a4 = acc[mi][jp*2 + tn];
                        mma16816(a4, ahi + mi*4, bhi + tn*2);
                        mma16816(a4, ahi + mi*4, blo + tn*2);
                        mma16816(a4, alo + mi*4, bhi + tn*2);
                    }
                }
            }
        }
        __syncthreads();
    }

    const int g = lane >> 2, tig = lane & 3;
    __nv_bfloat16* Dh = (mode == 0) ? g_Qh : (mode == 1) ? g_Kh : g_Vh;
    __nv_bfloat16* Dl = (mode == 0) ? g_Ql : (mode == 1) ? g_Kl : g_Vl;
#pragma unroll
    for (int mi = 0; mi < 2; mi++) {
#pragma unroll
        for (int nj = 0; nj < 8; nj++) {
            int col = colBase + wn*64 + nj*8 + tig*2;
            float b0 = __ldg(&bias[col]);
            float b1 = __ldg(&bias[col+1]);
#pragma unroll
            for (int rh = 0; rh < 2; rh++) {
                int row = rowBase + wm*32 + mi*16 + g + rh*8;
                float v0 = acc[mi][nj][rh*2+0] + b0;
                float v1 = acc[mi][nj][rh*2+1] + b1;
                if (mode < 3) {
                    int b_ = row >> 11, s_ = row & (SS - 1);
                    int h_ = col >> 6,  d_ = col & 63;
                    size_t idx = (size_t)(((b_*HH) + h_)*SS + s_)*DHD + d_;
                    unsigned h2, l2;
                    split_pair(v0, v1, h2, l2);
                    *(unsigned*)(Dh + idx) = h2;
                    *(unsigned*)(Dl + idx) = l2;
                } else {
                    float2 w2 = make_float2(v0, v1);
                    *(float2*)(out_ext + (size_t)row * DD + col) = w2;
                }
            }
        }
    }
}

// ---------------------------------------------------------------------------
// Fused attention (HMMA): pass A computes row sums l (QK + exp, no stores;
// 3-buffer ring, single sync per tile); pass B recomputes the identical t,
// writes p = t/l directly (the only attn-matrix traffic), and O += P V.
// ---------------------------------------------------------------------------
#define KSTR 144
#define KPLANE (128*KSTR)                  // 18432
#define PSTR2 272
#define PPL2 (128*PSTR2)                   // 34816
#define FQ 0
#define FK (2*KPLANE)                      // 36864
#define FV (4*KPLANE)                      // 73728 (2 stages x 36864)
#define FP (8*KPLANE)                      // 147456 (Ph, Pl)
#define FRED (FP + 2*PPL2)                 // 217088
#define FLI (FRED + 1024)                  // 218112
#define S_FUSED (FLI + 512)                // 218624

__global__ __launch_bounds__(256) void attn_fused(float* __restrict__ attn)
{
    extern __shared__ char sm[];
    const unsigned sb = s2u(sm);
    const int qt = (SS/128 - 1) - blockIdx.x;   // heavy CTAs first
    const int h = blockIdx.y, b = blockIdx.z;
    const int bh = b*HH + h;
    const int tid = threadIdx.x, wid = tid>>5, lane = tid&31;
    const int wm = wid>>1, wn = wid&1;
    const int g = lane>>2, tig = lane&3;
    const int qtb = qt*128;

    float* attn_bh = attn + (size_t)bh*SS*SS;
    float* redl = (float*)(sm + FRED);
    float* li = (float*)(sm + FLI);

    // zero-fill upper triangle (fire-and-forget streaming stores)
    {
        float4 z4 = make_float4(0.f, 0.f, 0.f, 0.f);
        for (int kt = qt + 1; kt < SS/128; kt++)
            for (int v = tid; v < 4096; v += 256) {
                int r = v>>5, c4 = (v&31)<<2;
                __stcs((float4*)(attn_bh + (size_t)(qtb + r)*SS + kt*128 + c4), z4);
            }
    }

    // Q planes (bundled with first K group)
    for (int i = tid; i < 2048; i += 256) {
        int pl = i >> 10, r = (i >> 3) & 127, sg = i & 7;
        const __nv_bfloat16* src =
            (pl ? g_Ql : g_Qh) + (size_t)(bh*SS + qtb + r)*DHD + sg*8;
        cpa16(sb + FQ + (unsigned)pl*KPLANE + (unsigned)r*KSTR + sg*16, src);
    }
    auto ISSUE_K = [&](int kt, unsigned dstbase) {
        const int ktb = kt*128;
        for (int i = tid; i < 2048; i += 256) {
            int pl = i >> 10, r = (i >> 3) & 127, sg = i & 7;
            const __nv_bfloat16* src =
                (pl ? g_Kl : g_Kh) + (size_t)(bh*SS + ktb + r)*DHD + sg*8;
            cpa16(dstbase + (unsigned)pl*KPLANE + (unsigned)r*KSTR + sg*16, src);
        }
    };
    auto ISSUE_V = [&](int kt) {
        const unsigned st = sb + FV + (unsigned)(kt & 1) * (2*KPLANE);
        const int ktb = kt*128;
        for (int i = tid; i < 2048; i += 256) {
            int pl = i >> 10, r = (i >> 3) & 127, sg = i & 7;
            const __nv_bfloat16* src =
                (pl ? g_Vl : g_Vh) + (size_t)(bh*SS + ktb + r)*DHD + sg*8;
            cpa16(st + (unsigned)pl*KPLANE + (unsigned)r*KSTR + sg*16, src);
        }
    };

    const int a_row = wm*32 + (lane&15);
    const int a_c8  = (lane>>4) << 3;
    const int b_row = wn*64 + (((lane>>4)&1)<<3) + (lane&7);
    const int b_c8  = ((lane>>3)&1) << 3;

    // ======== pass A: row sums only (3-buffer ring: FK, FV+0, FV+1) ========
    auto PA_BASE = [&](int kt) -> unsigned { return sb + FK + (unsigned)(kt % 3) * (2*KPLANE); };
    ISSUE_K(0, PA_BASE(0)); CP_COMMIT();
    float rsum[4] = {0.f, 0.f, 0.f, 0.f};

    for (int kt = 0; kt <= qt; kt++) {
        if (kt < qt) { ISSUE_K(kt + 1, PA_BASE(kt + 1)); CP_COMMIT(); CP_WAIT1(); }
        else         { CP_WAIT0(); }
        __syncthreads();                   // single sync per tile (ring depth 3)

        const unsigned sKh = PA_BASE(kt);
        const unsigned sKl = sKh + KPLANE;

        float acc[2][8][4];
#pragma unroll
        for (int i = 0; i < 2; i++)
#pragma unroll
            for (int j = 0; j < 8; j++)
#pragma unroll
                for (int v = 0; v < 4; v++) acc[i][j][v] = 0.f;

#pragma unroll
        for (int ks = 0; ks < 4; ks++) {
            unsigned arow = (unsigned)a_row * KSTR + (unsigned)(ks*16 + a_c8)*2;
            unsigned ahi[2][4], alo[2][4];
            ldm_x4(ahi[0], sb + FQ + arow);
            ldm_x4(alo[0], sb + FQ + KPLANE + arow);
            ldm_x4(ahi[1], sb + FQ + arow + 16*KSTR);
            ldm_x4(alo[1], sb + FQ + KPLANE + arow + 16*KSTR);
#pragma unroll
            for (int jp = 0; jp < 4; jp++) {
                unsigned br = (unsigned)(b_row + jp*16)*KSTR
                            + (unsigned)(ks*16 + b_c8)*2;
                unsigned bhi[4], blo[4];
                ldm_x4(bhi, sKh + br);
                ldm_x4(blo, sKl + br);
#pragma unroll
                for (int tn = 0; tn < 2; tn++) {
#pragma unroll
                    for (int mi = 0; mi < 2; mi++) {
                        float* a4 = acc[mi][jp*2+tn];
                        mma16816(a4, ahi[mi], bhi + tn*2);
                        mma16816(a4, ahi[mi], blo + tn*2);
                        mma16816(a4, alo[mi], bhi + tn*2);
                    }
                }
            }
        }

        const bool diag = (kt == qt);
#pragma unroll
        for (int mi = 0; mi < 2; mi++) {
#pragma unroll
            for (int rh = 0; rh < 2; rh++) {
                int qgl = wm*32 + mi*16 + g + rh*8;
#pragma unroll
                for (int nj = 0; nj < 8; nj++) {
                    int kgl = wn*64 + nj*8 + tig*2;
                    float t0 = __expf(fmaf(acc[mi][nj][rh*2+0], ATTN_SCALE, -CSHIFT));
                    float t1 = __expf(fmaf(acc[mi][nj][rh*2+1], ATTN_SCALE, -CSHIFT));
                    if (diag) {
                        if (kgl   > qgl) t0 = 0.f;
                        if (kgl+1 > qgl) t1 = 0.f;
                    }
                    rsum[mi*2+rh] += t0 + t1;
                }
            }
        }
    }

    // reduce rsum -> li (1/l) in SMEM
#pragma unroll
    for (int i = 0; i < 4; i++) {
        rsum[i] += __shfl_xor_sync(0xffffffff, rsum[i], 1);
        rsum[i] += __shfl_xor_sync(0xffffffff, rsum[i], 2);
    }
    __syncthreads();                       // all pass-A MMA/buffer use done
    if (tig == 0) {
#pragma unroll
        for (int i = 0; i < 4; i++) {
            int rl = wm*32 + (i>>1)*16 + g + (i&1)*8;
            redl[rl*2 + wn] = rsum[i];
        }
    }
    __syncthreads();
    if (tid < 128) li[tid] = 1.f / (redl[tid*2] + redl[tid*2+1]);
    __syncthreads();

    // ======== pass B: recompute t, write p, O += P V ========
    ISSUE_K(0, sb + FK); ISSUE_V(0); CP_COMMIT();

    float accO[2][4][4];
#pragma unroll
    for (int i = 0; i < 2; i++)
#pragma unroll
        for (int j = 0; j < 4; j++)
#pragma unroll
            for (int v = 0; v < 4; v++) accO[i][j][v] = 0.f;

    for (int kt = 0; kt <= qt; kt++) {
        const int ktb = kt*128;
        CP_WAIT0();
        __syncthreads();                   // K(kt), V(kt) ready

        float acc[2][8][4];
#pragma unroll
        for (int i = 0; i < 2; i++)
#pragma unroll
            for (int j = 0; j < 8; j++)
#pragma unroll
                for (int v = 0; v < 4; v++) acc[i][j][v] = 0.f;

#pragma unroll
        for (int ks = 0; ks < 4; ks++) {
            unsigned arow = (unsigned)a_row * KSTR + (unsigned)(ks*16 + a_c8)*2;
            unsigned ahi[2][4], alo[2][4];
            ldm_x4(ahi[0], sb + FQ + arow);
            ldm_x4(alo[0], sb + FQ + KPLANE + arow);
            ldm_x4(ahi[1], sb + FQ + arow + 16*KSTR);
            ldm_x4(alo[1], sb + FQ + KPLANE + arow + 16*KSTR);
#pragma unroll
            for (int jp = 0; jp < 4; jp++) {
                unsigned br = (unsigned)(b_row + jp*16)*KSTR
                            + (unsigned)(ks*16 + b_c8)*2;
                unsigned bhi[4], blo[4];
                ldm_x4(bhi, sb + FK + br);
                ldm_x4(blo, sb + FK + KPLANE + br);
#pragma unroll
                for (int tn = 0; tn < 2; tn++) {
#pragma unroll
                    for (int mi = 0; mi < 2; mi++) {
                        float* a4 = acc[mi][jp*2+tn];
                        mma16816(a4, ahi[mi], bhi + tn*2);
                        mma16816(a4, ahi[mi], blo + tn*2);
                        mma16816(a4, alo[mi], bhi + tn*2);
                    }
                }
            }
        }

        // epilogue: p = t * li[row]; write p (streaming) + P planes (STS)
        const bool diag = (kt == qt);
#pragma unroll
        for (int mi = 0; mi < 2; mi++) {
#pragma unroll
            for (int rh = 0; rh < 2; rh++) {
                int qgl = wm*32 + mi*16 + g + rh*8;
                float liv = li[qgl];
#pragma unroll
                for (int nj = 0; nj < 8; nj++) {
                    int kgl = wn*64 + nj*8 + tig*2;
                    float t0 = __expf(fmaf(acc[mi][nj][rh*2+0], ATTN_SCALE, -CSHIFT));
                    float t1 = __expf(fmaf(acc[mi][nj][rh*2+1], ATTN_SCALE, -CSHIFT));
                    if (diag) {
                        if (kgl   > qgl) t0 = 0.f;
                        if (kgl+1 > qgl) t1 = 0.f;
                    }
                    float p0 = t0 * liv, p1 = t1 * liv;
                    __stcs((float2*)(attn_bh + (size_t)(qtb+qgl)*SS + ktb + kgl),
                           make_float2(p0, p1));
                    unsigned h2, l2;
                    split_pair(p0, p1, h2, l2);
                    unsigned so = (unsigned)qgl*PSTR2 + (unsigned)kgl*2;
                    *(unsigned*)(sm + FP + so)        = h2;
                    *(unsigned*)(sm + FP + PPL2 + so) = l2;
                }
            }
        }
        __syncthreads();                   // P planes visible; K consumed

        if (kt < qt) { ISSUE_K(kt + 1, sb + FK); ISSUE_V(kt + 1); CP_COMMIT(); }

        // O += P(128x128) @ V(128x64)   (overlaps next K/V loads)
        const unsigned sVh = sb + FV + (unsigned)(kt & 1) * (2*KPLANE);
        const unsigned sVl = sVh + KPLANE;
#pragma unroll
        for (int ks = 0; ks < 8; ks++) {
            unsigned arow = (unsigned)(wm*32 + (lane&15))*PSTR2
                          + (unsigned)(ks*16 + ((lane>>4)<<3))*2;
            unsigned ahi[2][4], alo[2][4];
            ldm_x4(ahi[0], sb + FP + arow);
            ldm_x4(alo[0], sb + FP + PPL2 + arow);
            ldm_x4(ahi[1], sb + FP + arow + 16*PSTR2);
            ldm_x4(alo[1], sb + FP + PPL2 + arow + 16*PSTR2);
#pragma unroll
            for (int jp = 0; jp < 2; jp++) {
                unsigned brow = (unsigned)(ks*16 + (((lane>>3)&1)<<3) + (lane&7))*KSTR
                              + (unsigned)(wn*32 + jp*16 + (((lane>>4)&1)<<3))*2;
                unsigned bhi[4], blo[4];
                ldm_x4_t(bhi, sVh + brow);
                ldm_x4_t(blo, sVl + brow);
#pragma unroll
                for (int tn = 0; tn < 2; tn++) {
#pragma unroll
                    for (int mi = 0; mi < 2; mi++) {
                        float* a4 = accO[mi][jp*2+tn];
                        mma16816(a4, ahi[mi], bhi + tn*2);
                        mma16816(a4, ahi[mi], blo + tn*2);
                        mma16816(a4, alo[mi], bhi + tn*2);
                    }
                }
            }
        }
    }

    // write O planes (bf16 hi/lo) for the output projection
#pragma unroll
    for (int mi = 0; mi < 2; mi++) {
#pragma unroll
        for (int rh = 0; rh < 2; rh++) {
            int qg = qtb + wm*32 + mi*16 + g + rh*8;
            int n = b*SS + qg;
#pragma unroll
            for (int nj = 0; nj < 4; nj++) {
                int dd = h*DHD + wn*32 + nj*8 + tig*2;
                unsigned h2, l2;
                split_pair(accO[mi][nj][rh*2+0], accO[mi][nj][rh*2+1], h2, l2);
                size_t idx = (size_t)n * DD + dd;
                *(unsigned*)(g_Oh + idx) = h2;
                *(unsigned*)(g_Ol + idx) = l2;
            }
        }
    }
}

// ---------------------------------------------------------------------------
extern "C" void kernel_launch(void* const* d_in, const int* in_sizes, int n_in,
                              void* d_out, int out_size)
{
    const float* qkv[3] = {nullptr, nullptr, nullptr};
    const float* Wm[4]  = {nullptr, nullptr, nullptr, nullptr};
    const float* bm[4]  = {nullptr, nullptr, nullptr, nullptr};
    int nq = 0, nw = 0, nb = 0;
    for (int i = 0; i < n_in; i++) {
        int sz = in_sizes[i];
        if (sz == NROWS*DD)      { if (nq < 3) qkv[nq++] = (const float*)d_in[i]; }
        else if (sz == DD*DD)    { if (nw < 4) Wm[nw++]  = (const float*)d_in[i]; }
        else if (sz == DD)       { if (nb < 4) bm[nb++]  = (const float*)d_in[i]; }
    }

    float* out  = (float*)d_out;
    float* attn = out + (size_t)NROWS * DD;

    static int smem_set = 0;
    if (!smem_set) {
        cudaFuncSetAttribute(proj_gemm_bf,
                             cudaFuncAttributeMaxDynamicSharedMemorySize, PROJ_SMEM);
        cudaFuncSetAttribute(attn_fused,
                             cudaFuncAttributeMaxDynamicSharedMemorySize, S_FUSED);
        smem_set = 1;
    }

    dim3 blk(256);
    prep_split<<<dim3(1024, 7), blk>>>(qkv[0], qkv[1], qkv[2],
                                       Wm[0], Wm[1], Wm[2], Wm[3]);

    dim3 ggrid(DD/128, NROWS/128);            // (8, 32)
    proj_gemm_bf<<<ggrid, blk, PROJ_SMEM>>>(bm[0], nullptr, 0);
    proj_gemm_bf<<<ggrid, blk, PROJ_SMEM>>>(bm[1], nullptr, 1);
    proj_gemm_bf<<<ggrid, blk, PROJ_SMEM>>>(bm[2], nullptr, 2);

    dim3 agrid(SS/128, HH, BB);               // (16, 16, 2)
    attn_fused<<<agrid, blk, S_FUSED>>>(attn);

    proj_gemm_bf<<<ggrid, blk, PROJ_SMEM>>>(bm[3], out, 3);

    (void)out_size;
}

// round 15
// speedup vs baseline: 1.0259x; 1.0259x over previous
#include <cuda_runtime.h>
#include <cuda_bf16.h>
#include <math.h>

#define BB 2
#define SS 2048
#define DD 1024
#define HH 16
#define DHD 64
#define NROWS (BB*SS)        // 4096
#define NBH (BB*HH)          // 32
#define ATTN_SCALE 0.125f
#define CSHIFT 8.0f          // constant softmax shift (shift-invariant)

// ---------------------------------------------------------------------------
// Device-global scratch: bf16 hi/lo planes.
// ---------------------------------------------------------------------------
__device__ __nv_bfloat16 g_Xh[3][NROWS*DD];   // split query/key/value
__device__ __nv_bfloat16 g_Xl[3][NROWS*DD];
__device__ __nv_bfloat16 g_Wh[4][DD*DD];      // split Wq/Wk/Wv/Wo
__device__ __nv_bfloat16 g_Wl[4][DD*DD];
__device__ __nv_bfloat16 g_Qh[NBH*SS*DHD];    // [B,H,S,dh] planes
__device__ __nv_bfloat16 g_Ql[NBH*SS*DHD];
__device__ __nv_bfloat16 g_Kh[NBH*SS*DHD];
__device__ __nv_bfloat16 g_Kl[NBH*SS*DHD];
__device__ __nv_bfloat16 g_Vh[NBH*SS*DHD];
__device__ __nv_bfloat16 g_Vl[NBH*SS*DHD];
__device__ __nv_bfloat16 g_Oh[NROWS*DD];      // concat-heads planes
__device__ __nv_bfloat16 g_Ol[NROWS*DD];

// ===========================================================================
// helpers
// ===========================================================================
__device__ __forceinline__ unsigned s2u(const void* p) {
    unsigned a;
    asm("{ .reg .u64 t; cvta.to.shared.u64 t, %1; cvt.u32.u64 %0, t; }"
        : "=r"(a) : "l"(p));
    return a;
}
__device__ __forceinline__ void mma16816(float* c, const unsigned* a, const unsigned* b) {
    asm volatile(
        "mma.sync.aligned.m16n8k16.row.col.f32.bf16.bf16.f32 "
        "{%0,%1,%2,%3}, {%4,%5,%6,%7}, {%8,%9}, {%0,%1,%2,%3};"
        : "+f"(c[0]), "+f"(c[1]), "+f"(c[2]), "+f"(c[3])
        : "r"(a[0]), "r"(a[1]), "r"(a[2]), "r"(a[3]), "r"(b[0]), "r"(b[1]));
}
__device__ __forceinline__ void ldm_x4(unsigned* r, unsigned addr) {
    asm volatile("ldmatrix.sync.aligned.m8n8.x4.shared.b16 {%0,%1,%2,%3}, [%4];"
        : "=r"(r[0]), "=r"(r[1]), "=r"(r[2]), "=r"(r[3]) : "r"(addr));
}
__device__ __forceinline__ void ldm_x4_t(unsigned* r, unsigned addr) {
    asm volatile("ldmatrix.sync.aligned.m8n8.x4.trans.shared.b16 {%0,%1,%2,%3}, [%4];"
        : "=r"(r[0]), "=r"(r[1]), "=r"(r[2]), "=r"(r[3]) : "r"(addr));
}
// Truncation split of a pair of fp32 into packed bf16 hi/lo planes.
__device__ __forceinline__ void split_pair(float a, float b,
                                           unsigned& hi2, unsigned& lo2) {
    unsigned ua = __float_as_uint(a), ub = __float_as_uint(b);
    asm("prmt.b32 %0, %1, %2, 0x7632;" : "=r"(hi2) : "r"(ua), "r"(ub));
    float ha = __uint_as_float(ua & 0xFFFF0000u);
    float hb = __uint_as_float(ub & 0xFFFF0000u);
    float la = a - ha, lb = b - hb;
    asm("cvt.rn.bf16x2.f32 %0, %1, %2;" : "=r"(lo2) : "f"(lb), "f"(la));
}
__device__ __forceinline__ void cpa16(unsigned dst, const void* src) {
    asm volatile("cp.async.cg.shared.global [%0], [%1], 16;" :: "r"(dst), "l"(src));
}
#define CP_COMMIT() asm volatile("cp.async.commit_group;" ::: "memory")
#define CP_WAIT0()  asm volatile("cp.async.wait_group 0;" ::: "memory")
#define CP_WAIT1()  asm volatile("cp.async.wait_group 1;" ::: "memory")

// ---------------------------------------------------------------------------
// Prep: split inputs (q/k/v) and weights into bf16 hi/lo planes once.
// ---------------------------------------------------------------------------
__global__ __launch_bounds__(256) void prep_split(
    const float* __restrict__ q, const float* __restrict__ k,
    const float* __restrict__ v,
    const float* __restrict__ w0, const float* __restrict__ w1,
    const float* __restrict__ w2, const float* __restrict__ w3)
{
    const int z = blockIdx.y;
    const float* src;
    __nv_bfloat16 *dh, *dl;
    int n4;
    if (z < 3) {
        src = (z == 0) ? q : (z == 1) ? k : v;
        dh = g_Xh[z]; dl = g_Xl[z]; n4 = NROWS*DD/4;
    } else {
        int w = z - 3;
        src = (w == 0) ? w0 : (w == 1) ? w1 : (w == 2) ? w2 : w3;
        dh = g_Wh[w]; dl = g_Wl[w]; n4 = DD*DD/4;
    }
    for (int i = blockIdx.x * 256 + threadIdx.x; i < n4; i += gridDim.x * 256) {
        float4 x = ((const float4*)src)[i];
        unsigned h01, l01, h23, l23;
        split_pair(x.x, x.y, h01, l01);
        split_pair(x.z, x.w, h23, l23);
        ((uint2*)dh)[i] = make_uint2(h01, h23);
        ((uint2*)dl)[i] = make_uint2(l01, l23);
    }
}

// ---------------------------------------------------------------------------
// Projection GEMM (HMMA, bf16 planes, cp.async double-buffered).
// Sequential launches keep the ~41 MB working set L2-resident.
// ---------------------------------------------------------------------------
#define PROWB 80
#define PPLANE 10240
#define PSTAGE (4*PPLANE)
#define PROJ_SMEM (2*PSTAGE)               // 81920

__global__ __launch_bounds__(256) void proj_gemm_bf(
    const float* __restrict__ bias, float* __restrict__ out_ext, int mode)
{
    extern __shared__ char smem[];
    const unsigned sb = s2u(smem);
    const int tid = threadIdx.x, wid = tid >> 5, lane = tid & 31;
    const int wm = wid >> 1, wn = wid & 1;
    const int rowBase = blockIdx.y * 128;
    const int colBase = blockIdx.x * 128;

    const __nv_bfloat16* Xh = (mode == 3) ? g_Oh : g_Xh[mode];
    const __nv_bfloat16* Xl = (mode == 3) ? g_Ol : g_Xl[mode];
    const __nv_bfloat16* Wh = g_Wh[mode];
    const __nv_bfloat16* Wl = g_Wl[mode];

    float acc[2][8][4];
#pragma unroll
    for (int i = 0; i < 2; i++)
#pragma unroll
        for (int j = 0; j < 8; j++)
#pragma unroll
            for (int v = 0; v < 4; v++) acc[i][j][v] = 0.f;

    auto ISSUE = [&](int c) {
        const int k0 = c * 32;
        const unsigned st = sb + (unsigned)(c & 1) * PSTAGE;
        for (int i = tid; i < 2048; i += 256) {
            int pl = i >> 9, r = (i >> 2) & 127, sg = i & 3;
            const __nv_bfloat16* srcp;
            if (pl == 0)      srcp = Xh + (size_t)(rowBase + r) * DD + k0 + sg*8;
            else if (pl == 1) srcp = Xl + (size_t)(rowBase + r) * DD + k0 + sg*8;
            else if (pl == 2) srcp = Wh + (size_t)(colBase + r) * DD + k0 + sg*8;
            else              srcp = Wl + (size_t)(colBase + r) * DD + k0 + sg*8;
            cpa16(st + (unsigned)pl * PPLANE + (unsigned)r * PROWB + sg*16, srcp);
        }
    };

    ISSUE(0); CP_COMMIT();

    const int a_row = wm*32 + (lane & 15);
    const int a_c8  = (lane >> 4) << 3;
    const int b_row = wn*64 + (((lane >> 4) & 1) << 3) + (lane & 7);
    const int b_c8  = ((lane >> 3) & 1) << 3;

    for (int c = 0; c < 32; c++) {
        if (c < 31) { ISSUE(c + 1); CP_COMMIT(); CP_WAIT1(); }
        else        { CP_WAIT0(); }
        __syncthreads();

        const unsigned sA  = sb + (unsigned)(c & 1) * PSTAGE;
        const unsigned sAl = sA + PPLANE;
        const unsigned sBh = sA + 2*PPLANE;
        const unsigned sBl = sA + 3*PPLANE;

#pragma unroll
        for (int ks = 0; ks < 2; ks++) {
            unsigned ahi[8], alo[8];
#pragma unroll
            for (int t = 0; t < 2; t++) {
                unsigned ar = (unsigned)(a_row + t*16) * PROWB
                            + (unsigned)(ks*16 + a_c8) * 2;
                ldm_x4(ahi + t*4, sA  + ar);
                ldm_x4(alo + t*4, sAl + ar);
            }
#pragma unroll
            for (int jp = 0; jp < 4; jp++) {
                unsigned br = (unsigned)(b_row + jp*16) * PROWB
                            + (unsigned)(ks*16 + b_c8) * 2;
                unsigned bhi[4], blo[4];
                ldm_x4(bhi, sBh + br);
                ldm_x4(blo, sBl + br);
#pragma unroll
                for (int tn = 0; tn < 2; tn++) {
#pragma unroll
                    for (int mi = 0; mi < 2; mi++) {
                        float* a4 = acc[mi][jp*2 + tn];
                        mma16816(a4, ahi + mi*4, bhi + tn*2);
                        mma16816(a4, ahi + mi*4, blo + tn*2);
                        mma16816(a4, alo + mi*4, bhi + tn*2);
                    }
                }
            }
        }
        __syncthreads();
    }

    const int g = lane >> 2, tig = lane & 3;
    __nv_bfloat16* Dh = (mode == 0) ? g_Qh : (mode == 1) ? g_Kh : g_Vh;
    __nv_bfloat16* Dl = (mode == 0) ? g_Ql : (mode == 1) ? g_Kl : g_Vl;
#pragma unroll
    for (int mi = 0; mi < 2; mi++) {
#pragma unroll
        for (int nj = 0; nj < 8; nj++) {
            int col = colBase + wn*64 + nj*8 + tig*2;
            float b0 = __ldg(&bias[col]);
            float b1 = __ldg(&bias[col+1]);
#pragma unroll
            for (int rh = 0; rh < 2; rh++) {
                int row = rowBase + wm*32 + mi*16 + g + rh*8;
                float v0 = acc[mi][nj][rh*2+0] + b0;
                float v1 = acc[mi][nj][rh*2+1] + b1;
                if (mode < 3) {
                    int b_ = row >> 11, s_ = row & (SS - 1);
                    int h_ = col >> 6,  d_ = col & 63;
                    size_t idx = (size_t)(((b_*HH) + h_)*SS + s_)*DHD + d_;
                    unsigned h2, l2;
                    split_pair(v0, v1, h2, l2);
                    *(unsigned*)(Dh + idx) = h2;
                    *(unsigned*)(Dl + idx) = l2;
                } else {
                    float2 w2 = make_float2(v0, v1);
                    *(float2*)(out_ext + (size_t)row * DD + col) = w2;
                }
            }
        }
    }
}

// ---------------------------------------------------------------------------
// Fused attention (HMMA), 512 threads / 16 warps (4m x 4n) to hide latency
// at 1 CTA/SM. Pass A: row sums (3-buffer ring). Pass B: recompute t, write
// p directly, O += P V.
// ---------------------------------------------------------------------------
#define KSTR 144
#define KPLANE (128*KSTR)                  // 18432
#define PSTR2 272
#define PPL2 (128*PSTR2)                   // 34816
#define FQ 0
#define FK (2*KPLANE)                      // 36864
#define FV (4*KPLANE)                      // 73728 (2 stages x 36864)
#define FP (8*KPLANE)                      // 147456 (Ph, Pl)
#define FRED (FP + 2*PPL2)                 // 217088
#define FLI (FRED + 2048)                  // 219136
#define S_FUSED (FLI + 512)                // 219648

__global__ __launch_bounds__(512) void attn_fused(float* __restrict__ attn)
{
    extern __shared__ char sm[];
    const unsigned sb = s2u(sm);
    const int qt = (SS/128 - 1) - blockIdx.x;   // heavy CTAs first
    const int h = blockIdx.y, b = blockIdx.z;
    const int bh = b*HH + h;
    const int tid = threadIdx.x, wid = tid>>5, lane = tid&31;
    const int wm = wid>>2, wn = wid&3;          // 4m x 4n warp grid
    const int g = lane>>2, tig = lane&3;
    const int qtb = qt*128;

    float* attn_bh = attn + (size_t)bh*SS*SS;
    float* redl = (float*)(sm + FRED);          // [128][4]
    float* li = (float*)(sm + FLI);

    // zero-fill upper triangle (fire-and-forget streaming stores)
    {
        float4 z4 = make_float4(0.f, 0.f, 0.f, 0.f);
        for (int kt = qt + 1; kt < SS/128; kt++)
            for (int v = tid; v < 4096; v += 512) {
                int r = v>>5, c4 = (v&31)<<2;
                __stcs((float4*)(attn_bh + (size_t)(qtb + r)*SS + kt*128 + c4), z4);
            }
    }

    // Q planes (bundled with first K group)
    for (int i = tid; i < 2048; i += 512) {
        int pl = i >> 10, r = (i >> 3) & 127, sg = i & 7;
        const __nv_bfloat16* src =
            (pl ? g_Ql : g_Qh) + (size_t)(bh*SS + qtb + r)*DHD + sg*8;
        cpa16(sb + FQ + (unsigned)pl*KPLANE + (unsigned)r*KSTR + sg*16, src);
    }
    auto ISSUE_K = [&](int kt, unsigned dstbase) {
        const int ktb = kt*128;
        for (int i = tid; i < 2048; i += 512) {
            int pl = i >> 10, r = (i >> 3) & 127, sg = i & 7;
            const __nv_bfloat16* src =
                (pl ? g_Kl : g_Kh) + (size_t)(bh*SS + ktb + r)*DHD + sg*8;
            cpa16(dstbase + (unsigned)pl*KPLANE + (unsigned)r*KSTR + sg*16, src);
        }
    };
    auto ISSUE_V = [&](int kt) {
        const unsigned st = sb + FV + (unsigned)(kt & 1) * (2*KPLANE);
        const int ktb = kt*128;
        for (int i = tid; i < 2048; i += 512) {
            int pl = i >> 10, r = (i >> 3) & 127, sg = i & 7;
            const __nv_bfloat16* src =
                (pl ? g_Vl : g_Vh) + (size_t)(bh*SS + ktb + r)*DHD + sg*8;
            cpa16(st + (unsigned)pl*KPLANE + (unsigned)r*KSTR + sg*16, src);
        }
    };

    const int a_row = wm*32 + (lane&15);
    const int a_c8  = (lane>>4) << 3;
    const int b_row0 = wn*32 + (((lane>>4)&1)<<3) + (lane&7);  // + jp*16
    const int b_c8  = ((lane>>3)&1) << 3;

    // ======== pass A: row sums only (3-buffer ring: FK, FV+0, FV+1) ========
    auto PA_BASE = [&](int kt) -> unsigned { return sb + FK + (unsigned)(kt % 3) * (2*KPLANE); };
    ISSUE_K(0, PA_BASE(0)); CP_COMMIT();
    float rsum[4] = {0.f, 0.f, 0.f, 0.f};

    for (int kt = 0; kt <= qt; kt++) {
        if (kt < qt) { ISSUE_K(kt + 1, PA_BASE(kt + 1)); CP_COMMIT(); CP_WAIT1(); }
        else         { CP_WAIT0(); }
        __syncthreads();

        const unsigned sKh = PA_BASE(kt);
        const unsigned sKl = sKh + KPLANE;

        float acc[2][4][4];
#pragma unroll
        for (int i = 0; i < 2; i++)
#pragma unroll
            for (int j = 0; j < 4; j++)
#pragma unroll
                for (int v = 0; v < 4; v++) acc[i][j][v] = 0.f;

#pragma unroll
        for (int ks = 0; ks < 4; ks++) {
            unsigned arow = (unsigned)a_row * KSTR + (unsigned)(ks*16 + a_c8)*2;
            unsigned ahi[2][4], alo[2][4];
            ldm_x4(ahi[0], sb + FQ + arow);
            ldm_x4(alo[0], sb + FQ + KPLANE + arow);
            ldm_x4(ahi[1], sb + FQ + arow + 16*KSTR);
            ldm_x4(alo[1], sb + FQ + KPLANE + arow + 16*KSTR);
#pragma unroll
            for (int jp = 0; jp < 2; jp++) {
                unsigned br = (unsigned)(b_row0 + jp*16)*KSTR
                            + (unsigned)(ks*16 + b_c8)*2;
                unsigned bhi[4], blo[4];
                ldm_x4(bhi, sKh + br);
                ldm_x4(blo, sKl + br);
#pragma unroll
                for (int tn = 0; tn < 2; tn++) {
#pragma unroll
                    for (int mi = 0; mi < 2; mi++) {
                        float* a4 = acc[mi][jp*2+tn];
                        mma16816(a4, ahi[mi], bhi + tn*2);
                        mma16816(a4, ahi[mi], blo + tn*2);
                        mma16816(a4, alo[mi], bhi + tn*2);
                    }
                }
            }
        }

        const bool diag = (kt == qt);
#pragma unroll
        for (int mi = 0; mi < 2; mi++) {
#pragma unroll
            for (int rh = 0; rh < 2; rh++) {
                int qgl = wm*32 + mi*16 + g + rh*8;
#pragma unroll
                for (int nj = 0; nj < 4; nj++) {
                    int kgl = wn*32 + nj*8 + tig*2;
                    float t0 = __expf(fmaf(acc[mi][nj][rh*2+0], ATTN_SCALE, -CSHIFT));
                    float t1 = __expf(fmaf(acc[mi][nj][rh*2+1], ATTN_SCALE, -CSHIFT));
                    if (diag) {
                        if (kgl   > qgl) t0 = 0.f;
                        if (kgl+1 > qgl) t1 = 0.f;
                    }
                    rsum[mi*2+rh] += t0 + t1;
                }
            }
        }
    }

    // reduce rsum -> li (1/l) in SMEM
#pragma unroll
    for (int i = 0; i < 4; i++) {
        rsum[i] += __shfl_xor_sync(0xffffffff, rsum[i], 1);
        rsum[i] += __shfl_xor_sync(0xffffffff, rsum[i], 2);
    }
    __syncthreads();                       // all pass-A MMA/buffer use done
    if (tig == 0) {
#pragma unroll
        for (int i = 0; i < 4; i++) {
            int rl = wm*32 + (i>>1)*16 + g + (i&1)*8;
            redl[rl*4 + wn] = rsum[i];
        }
    }
    __syncthreads();
    if (tid < 128)
        li[tid] = 1.f / (redl[tid*4] + redl[tid*4+1] + redl[tid*4+2] + redl[tid*4+3]);
    __syncthreads();

    // ======== pass B: recompute t, write p, O += P V ========
    ISSUE_K(0, sb + FK); ISSUE_V(0); CP_COMMIT();

    float accO[2][2][4];
#pragma unroll
    for (int i = 0; i < 2; i++)
#pragma unroll
        for (int j = 0; j < 2; j++)
#pragma unroll
            for (int v = 0; v < 4; v++) accO[i][j][v] = 0.f;

    for (int kt = 0; kt <= qt; kt++) {
        const int ktb = kt*128;
        CP_WAIT0();
        __syncthreads();                   // K(kt), V(kt) ready

        float acc[2][4][4];
#pragma unroll
        for (int i = 0; i < 2; i++)
#pragma unroll
            for (int j = 0; j < 4; j++)
#pragma unroll
                for (int v = 0; v < 4; v++) acc[i][j][v] = 0.f;

#pragma unroll
        for (int ks = 0; ks < 4; ks++) {
            unsigned arow = (unsigned)a_row * KSTR + (unsigned)(ks*16 + a_c8)*2;
            unsigned ahi[2][4], alo[2][4];
            ldm_x4(ahi[0], sb + FQ + arow);
            ldm_x4(alo[0], sb + FQ + KPLANE + arow);
            ldm_x4(ahi[1], sb + FQ + arow + 16*KSTR);
            ldm_x4(alo[1], sb + FQ + KPLANE + arow + 16*KSTR);
#pragma unroll
            for (int jp = 0; jp < 2; jp++) {
                unsigned br = (unsigned)(b_row0 + jp*16)*KSTR
                            + (unsigned)(ks*16 + b_c8)*2;
                unsigned bhi[4], blo[4];
                ldm_x4(bhi, sb + FK + br);
                ldm_x4(blo, sb + FK + KPLANE + br);
#pragma unroll
                for (int tn = 0; tn < 2; tn++) {
#pragma unroll
                    for (int mi = 0; mi < 2; mi++) {
                        float* a4 = acc[mi][jp*2+tn];
                        mma16816(a4, ahi[mi], bhi + tn*2);
                        mma16816(a4, ahi[mi], blo + tn*2);
                        mma16816(a4, alo[mi], bhi + tn*2);
                    }
                }
            }
        }

        // epilogue: p = t * li[row]; write p (streaming) + P planes (STS)
        const bool diag = (kt == qt);
#pragma unroll
        for (int mi = 0; mi < 2; mi++) {
#pragma unroll
            for (int rh = 0; rh < 2; rh++) {
                int qgl = wm*32 + mi*16 + g + rh*8;
                float liv = li[qgl];
#pragma unroll
                for (int nj = 0; nj < 4; nj++) {
                    int kgl = wn*32 + nj*8 + tig*2;
                    float t0 = __expf(fmaf(acc[mi][nj][rh*2+0], ATTN_SCALE, -CSHIFT));
                    float t1 = __expf(fmaf(acc[mi][nj][rh*2+1], ATTN_SCALE, -CSHIFT));
                    if (diag) {
                        if (kgl   > qgl) t0 = 0.f;
                        if (kgl+1 > qgl) t1 = 0.f;
                    }
                    float p0 = t0 * liv, p1 = t1 * liv;
                    __stcs((float2*)(attn_bh + (size_t)(qtb+qgl)*SS + ktb + kgl),
                           make_float2(p0, p1));
                    unsigned h2, l2;
                    split_pair(p0, p1, h2, l2);
                    unsigned so = (unsigned)qgl*PSTR2 + (unsigned)kgl*2;
                    *(unsigned*)(sm + FP + so)        = h2;
                    *(unsigned*)(sm + FP + PPL2 + so) = l2;
                }
            }
        }
        __syncthreads();                   // P planes visible; K consumed

        if (kt < qt) { ISSUE_K(kt + 1, sb + FK); ISSUE_V(kt + 1); CP_COMMIT(); }

        // O += P(128x128) @ V(128x64); warp tile 32 rows x 16 cols
        const unsigned sVh = sb + FV + (unsigned)(kt & 1) * (2*KPLANE);
        const unsigned sVl = sVh + KPLANE;
#pragma unroll
        for (int ks = 0; ks < 8; ks++) {
            unsigned arow = (unsigned)(wm*32 + (lane&15))*PSTR2
                          + (unsigned)(ks*16 + ((lane>>4)<<3))*2;
            unsigned ahi[2][4], alo[2][4];
            ldm_x4(ahi[0], sb + FP + arow);
            ldm_x4(alo[0], sb + FP + PPL2 + arow);
            ldm_x4(ahi[1], sb + FP + arow + 16*PSTR2);
            ldm_x4(alo[1], sb + FP + PPL2 + arow + 16*PSTR2);

            unsigned brow = (unsigned)(ks*16 + (((lane>>3)&1)<<3) + (lane&7))*KSTR
                          + (unsigned)(wn*16 + (((lane>>4)&1)<<3))*2;
            unsigned bhi[4], blo[4];
            ldm_x4_t(bhi, sVh + brow);
            ldm_x4_t(blo, sVl + brow);
#pragma unroll
            for (int tn = 0; tn < 2; tn++) {
#pragma unroll
                for (int mi = 0; mi < 2; mi++) {
                    float* a4 = accO[mi][tn];
                    mma16816(a4, ahi[mi], bhi + tn*2);
                    mma16816(a4, ahi[mi], blo + tn*2);
                    mma16816(a4, alo[mi], bhi + tn*2);
                }
            }
        }
    }

    // write O planes (bf16 hi/lo) for the output projection
#pragma unroll
    for (int mi = 0; mi < 2; mi++) {
#pragma unroll
        for (int rh = 0; rh < 2; rh++) {
            int qg = qtb + wm*32 + mi*16 + g + rh*8;
            int n = b*SS + qg;
#pragma unroll
            for (int nj = 0; nj < 2; nj++) {
                int dd = h*DHD + wn*16 + nj*8 + tig*2;
                unsigned h2, l2;
                split_pair(accO[mi][nj][rh*2+0], accO[mi][nj][rh*2+1], h2, l2);
                size_t idx = (size_t)n * DD + dd;
                *(unsigned*)(g_Oh + idx) = h2;
                *(unsigned*)(g_Ol + idx) = l2;
            }
        }
    }
}

// ---------------------------------------------------------------------------
extern "C" void kernel_launch(void* const* d_in, const int* in_sizes, int n_in,
                              void* d_out, int out_size)
{
    const float* qkv[3] = {nullptr, nullptr, nullptr};
    const float* Wm[4]  = {nullptr, nullptr, nullptr, nullptr};
    const float* bm[4]  = {nullptr, nullptr, nullptr, nullptr};
    int nq = 0, nw = 0, nb = 0;
    for (int i = 0; i < n_in; i++) {
        int sz = in_sizes[i];
        if (sz == NROWS*DD)      { if (nq < 3) qkv[nq++] = (const float*)d_in[i]; }
        else if (sz == DD*DD)    { if (nw < 4) Wm[nw++]  = (const float*)d_in[i]; }
        else if (sz == DD)       { if (nb < 4) bm[nb++]  = (const float*)d_in[i]; }
    }

    float* out  = (float*)d_out;
    float* attn = out + (size_t)NROWS * DD;

    static int smem_set = 0;
    if (!smem_set) {
        cudaFuncSetAttribute(proj_gemm_bf,
                             cudaFuncAttributeMaxDynamicSharedMemorySize, PROJ_SMEM);
        cudaFuncSetAttribute(attn_fused,
                             cudaFuncAttributeMaxDynamicSharedMemorySize, S_FUSED);
        smem_set = 1;
    }

    dim3 blk(256);
    prep_split<<<dim3(1024, 7), blk>>>(qkv[0], qkv[1], qkv[2],
                                       Wm[0], Wm[1], Wm[2], Wm[3]);

    dim3 ggrid(DD/128, NROWS/128);            // (8, 32)
    proj_gemm_bf<<<ggrid, blk, PROJ_SMEM>>>(bm[0], nullptr, 0);
    proj_gemm_bf<<<ggrid, blk, PROJ_SMEM>>>(bm[1], nullptr, 1);
    proj_gemm_bf<<<ggrid, blk, PROJ_SMEM>>>(bm[2], nullptr, 2);

    dim3 agrid(SS/128, HH, BB);               // (16, 16, 2)
    attn_fused<<<agrid, dim3(512), S_FUSED>>>(attn);

    proj_gemm_bf<<<ggrid, blk, PROJ_SMEM>>>(bm[3], out, 3);

    (void)out_size;
}